// round 9
// baseline (speedup 1.0000x reference)
#include <cuda_runtime.h>

// Log-sparse causal attention, B=4, L=2048, H=8, E=D=64, fp32.
// Query l attends keys l-d for d in OFF (17 offsets), d <= l.
// Half-warp (16 lanes) processes QG=4 consecutive queries, sharing K/V row
// loads across the group (45 distinct rows instead of 68).
// Score array split lo(8)/slot8/hi(8) keeps regs ~72 (occ ~44%).
// Loads UNCONDITIONAL clamped-address inside warp-uniform row-group guards:
// far row groups (e>=130) are skipped entirely when no query in the warp
// can attend them (grid-avg ~8% of all row work removed).

constexpr int Bc = 4, Lc = 2048, Hc = 8;
constexpr float SCALE = 0.125f;      // 1/sqrt(64)
constexpr int ROWSTR = Hc * 64;      // 512 elements per l-step

// 45 distinct relative rows e (row = l0 - e) covering all (j in 0..3, d in OFF)
__device__ constexpr int EREL[45] = {
    -3,-2,-1,0,1,2,3,4,5,6,7,8,9,10,11,12,13,
    18,19,20,21, 34,35,36,37, 66,67,68,69,
    130,131,132,133, 258,259,260,261, 514,515,516,517,
    1026,1027,1028,1029
};

// TIDX[ei][j] = slot t (index into OFF) with OFF[t] = EREL[ei] + j, or -1
__device__ constexpr int TIDX[45][4] = {
    {-1,-1,-1, 0}, {-1,-1, 0, 1}, {-1, 0, 1, 2}, { 0, 1, 2, 3},
    { 1, 2, 3, 4}, { 2, 3, 4, 5}, { 3, 4, 5, 6}, { 4, 5, 6, 7},
    { 5, 6, 7,-1}, { 6, 7,-1, 8}, { 7,-1, 8,-1}, {-1, 8,-1,-1},
    { 8,-1,-1,-1}, {-1,-1,-1, 9}, {-1,-1, 9,-1}, {-1, 9,-1,-1},
    { 9,-1,-1,-1},
    {-1,-1,-1,10}, {-1,-1,10,-1}, {-1,10,-1,-1}, {10,-1,-1,-1},
    {-1,-1,-1,11}, {-1,-1,11,-1}, {-1,11,-1,-1}, {11,-1,-1,-1},
    {-1,-1,-1,12}, {-1,-1,12,-1}, {-1,12,-1,-1}, {12,-1,-1,-1},
    {-1,-1,-1,13}, {-1,-1,13,-1}, {-1,13,-1,-1}, {13,-1,-1,-1},
    {-1,-1,-1,14}, {-1,-1,14,-1}, {-1,14,-1,-1}, {14,-1,-1,-1},
    {-1,-1,-1,15}, {-1,-1,15,-1}, {-1,15,-1,-1}, {15,-1,-1,-1},
    {-1,-1,-1,16}, {-1,-1,16,-1}, {-1,16,-1,-1}, {16,-1,-1,-1}
};

// Transpose-reduce of 8 values over a 16-lane half: lane u ends holding the
// full 16-lane sum of value index (u>>1)&7 (duplicated in lane pairs). 8 SHFLs.
__device__ __forceinline__ float txr8(const float* v, int lane) {
    const unsigned FULL = 0xffffffffu;
    const bool b8 = (lane & 8) != 0;
    float w[4];
    #pragma unroll
    for (int i = 0; i < 4; i++) {
        float own = b8 ? v[i + 4] : v[i];
        float oth = b8 ? v[i] : v[i + 4];
        w[i] = own + __shfl_xor_sync(FULL, oth, 8);
    }
    const bool b4 = (lane & 4) != 0;
    float x[2];
    #pragma unroll
    for (int i = 0; i < 2; i++) {
        float own = b4 ? w[i + 2] : w[i];
        float oth = b4 ? w[i] : w[i + 2];
        x[i] = own + __shfl_xor_sync(FULL, oth, 4);
    }
    const bool b2 = (lane & 2) != 0;
    float own = b2 ? x[1] : x[0];
    float oth = b2 ? x[0] : x[1];
    float y = own + __shfl_xor_sync(FULL, oth, 2);
    y += __shfl_xor_sync(FULL, y, 1);   // bit0 partner holds the same index
    return y;
}

__global__ __launch_bounds__(128, 7) void sparse_attn_skip(
    const float* __restrict__ Q,
    const float* __restrict__ K,
    const float* __restrict__ V,
    float* __restrict__ O)
{
    const unsigned FULL = 0xffffffffu;
    const int tid  = threadIdx.x;
    const int warp = tid >> 5;
    const int lane = tid & 31;
    const int half = lane >> 4;
    const int sub  = lane & 15;      // dim slice: floats [4*sub, 4*sub+4)

    // CTA = 32 consecutive queries of one (b,h). grid = 4*8*64 = 2048
    const int cta   = blockIdx.x;
    const int chunk = cta & 63;
    const int bh    = cta >> 6;
    const int h     = bh & 7;
    const int b     = bh >> 3;

    const int lwarp = chunk * 32 + warp * 8;           // warp-uniform base
    const int l0    = lwarp + half * 4;                // first of 4 queries
    const int lmax  = lwarp + 7;                       // warp-uniform max query

    const int rbase = ((b * Lc + l0) * Hc + h) * 64 + sub * 4;

    // load the 4 query rows
    float4 q0 = *reinterpret_cast<const float4*>(Q + rbase);
    float4 q1 = *reinterpret_cast<const float4*>(Q + rbase + ROWSTR);
    float4 q2 = *reinterpret_cast<const float4*>(Q + rbase + 2 * ROWSTR);
    float4 q3 = *reinterpret_cast<const float4*>(Q + rbase + 3 * ROWSTR);

    const int slot = (sub >> 1) & 7;                 // my lane's value index
    const int offlo = slot;                          // OFF[slot] for lo slots
    const int offhi = (1 << (slot + 3)) + 5;         // OFF[slot+9]: 13,21,...,1029
    const int halfbase = lane & 16;

    float ejlo[4], ejhi[4], e8r[4], inv[4];

// per-row K dot: row ei accumulated into slo/s8 or shi
#define KROW(ei, DST_LO, DST_S8, DST_HI) do {                                 \
        const int e = EREL[ei];                                               \
        const bool ok = (l0 >= e);                                            \
        const int addr = ok ? (rbase - e * ROWSTR) : rbase;                   \
        const float4 k = *reinterpret_cast<const float4*>(K + addr);          \
        _Pragma("unroll")                                                     \
        for (int j = 0; j < 4; j++) {                                         \
            const int t = TIDX[ei][j];                                        \
            if (t >= 0) {                                                     \
                const float4 qq = (j==0)?q0:(j==1)?q1:(j==2)?q2:q3;           \
                float p = qq.x * k.x;                                         \
                p = fmaf(qq.y, k.y, p);                                       \
                p = fmaf(qq.z, k.z, p);                                       \
                p = fmaf(qq.w, k.w, p);                                       \
                if (t < 8)       DST_LO[j][t] = p;                            \
                else if (t == 8) DST_S8[j] = p;                               \
                else             DST_HI[j][t - 9] = p;                        \
            }                                                                 \
        }                                                                     \
    } while (0)

    // ---------- Phase 1a: rows e=-3..9 -> slots 0..8 ----------
    {
        float slo[4][8];
        float s8[4] = {0.f, 0.f, 0.f, 0.f};
        float dummy_hi[4][8]; // never written here
        #pragma unroll
        for (int ei = 0; ei < 13; ei++) KROW(ei, slo, s8, dummy_hi);

        #pragma unroll
        for (int j = 0; j < 4; j++) {
            float zlo = txr8(&slo[j][0], lane);
            float z8  = s8[j];
            z8 += __shfl_xor_sync(FULL, z8, 8);
            z8 += __shfl_xor_sync(FULL, z8, 4);
            z8 += __shfl_xor_sync(FULL, z8, 2);
            z8 += __shfl_xor_sync(FULL, z8, 1);
            ejlo[j] = (l0 + j >= offlo) ? __expf(zlo * SCALE) : 0.f;
            e8r[j]  = (l0 + j >= 9)     ? __expf(z8  * SCALE) : 0.f;
        }
    }

    // ---------- Phase 1b: rows e=10..1029 -> slots 9..16 ----------
    {
        float shi[4][8] = {};   // zero-init: guarded-out slots stay 0
        float dummy_lo[4][8];
        float dummy_s8[4];
        #pragma unroll
        for (int ei = 13; ei < 29; ei++) KROW(ei, dummy_lo, dummy_s8, shi); // e=10..69
        // warp-uniform skip of far row groups
        if (lmax >= 130) {
            #pragma unroll
            for (int ei = 29; ei < 33; ei++) KROW(ei, dummy_lo, dummy_s8, shi);
            if (lmax >= 258) {
                #pragma unroll
                for (int ei = 33; ei < 37; ei++) KROW(ei, dummy_lo, dummy_s8, shi);
                if (lmax >= 514) {
                    #pragma unroll
                    for (int ei = 37; ei < 41; ei++) KROW(ei, dummy_lo, dummy_s8, shi);
                    if (lmax >= 1026) {
                        #pragma unroll
                        for (int ei = 41; ei < 45; ei++) KROW(ei, dummy_lo, dummy_s8, shi);
                    }
                }
            }
        }

        #pragma unroll
        for (int j = 0; j < 4; j++) {
            float zhi = txr8(&shi[j][0], lane);
            ejhi[j] = (l0 + j >= offhi) ? __expf(zhi * SCALE) : 0.f;
            // denominator: lanes u,u^1 hold duplicates -> butterfly {2,4,8}
            float sm = ejlo[j] + ejhi[j];
            sm += __shfl_xor_sync(FULL, sm, 2);
            sm += __shfl_xor_sync(FULL, sm, 4);
            sm += __shfl_xor_sync(FULL, sm, 8);
            inv[j] = __fdividef(1.f, sm + e8r[j]);
        }
    }

    // ---------- Phase 3: weighted V accumulation ----------
    float4 a0 = make_float4(0.f, 0.f, 0.f, 0.f);
    float4 a1 = a0, a2 = a0, a3 = a0;

#define VROW(ei) do {                                                         \
        const int e = EREL[ei];                                               \
        const bool ok = (l0 >= e);                                            \
        const int addr = ok ? (rbase - e * ROWSTR) : rbase;                   \
        const float4 v = *reinterpret_cast<const float4*>(V + addr);          \
        _Pragma("unroll")                                                     \
        for (int j = 0; j < 4; j++) {                                         \
            const int t = TIDX[ei][j];                                        \
            if (t >= 0) {                                                     \
                float w;                                                      \
                if (t == 8)      w = e8r[j];                                  \
                else if (t < 8)  w = __shfl_sync(FULL, ejlo[j], halfbase + 2*t);      \
                else             w = __shfl_sync(FULL, ejhi[j], halfbase + 2*(t-9));  \
                float4& a = (j==0)?a0:(j==1)?a1:(j==2)?a2:a3;                 \
                a.x = fmaf(w, v.x, a.x);                                      \
                a.y = fmaf(w, v.y, a.y);                                      \
                a.z = fmaf(w, v.z, a.z);                                      \
                a.w = fmaf(w, v.w, a.w);                                      \
            }                                                                 \
        }                                                                     \
    } while (0)

    #pragma unroll
    for (int ei = 0; ei < 29; ei++) VROW(ei);      // e=-3..69, straight-line
    if (lmax >= 130) {
        #pragma unroll
        for (int ei = 29; ei < 33; ei++) VROW(ei);
        if (lmax >= 258) {
            #pragma unroll
            for (int ei = 33; ei < 37; ei++) VROW(ei);
            if (lmax >= 514) {
                #pragma unroll
                for (int ei = 37; ei < 41; ei++) VROW(ei);
                if (lmax >= 1026) {
                    #pragma unroll
                    for (int ei = 41; ei < 45; ei++) VROW(ei);
                }
            }
        }
    }

    a0.x *= inv[0]; a0.y *= inv[0]; a0.z *= inv[0]; a0.w *= inv[0];
    a1.x *= inv[1]; a1.y *= inv[1]; a1.z *= inv[1]; a1.w *= inv[1];
    a2.x *= inv[2]; a2.y *= inv[2]; a2.z *= inv[2]; a2.w *= inv[2];
    a3.x *= inv[3]; a3.y *= inv[3]; a3.z *= inv[3]; a3.w *= inv[3];

    *reinterpret_cast<float4*>(O + rbase)              = a0;
    *reinterpret_cast<float4*>(O + rbase + ROWSTR)     = a1;
    *reinterpret_cast<float4*>(O + rbase + 2 * ROWSTR) = a2;
    *reinterpret_cast<float4*>(O + rbase + 3 * ROWSTR) = a3;
}

extern "C" void kernel_launch(void* const* d_in, const int* in_sizes, int n_in,
                              void* d_out, int out_size)
{
    const float* Q = (const float*)d_in[0];
    const float* K = (const float*)d_in[1];
    const float* V = (const float*)d_in[2];
    float* O = (float*)d_out;

    const int nblocks = Bc * Hc * (Lc / 32); // 2048
    sparse_attn_skip<<<nblocks, 128>>>(Q, K, V, O);
}